// round 9
// baseline (speedup 1.0000x reference)
#include <cuda_runtime.h>
#include <cstdint>

// Problem constants
#define N_BATCH 2
#define CIN     256
#define COUT    256
#define KTOT    2304      // CIN * 9
#define MTOT    32768     // N * H * W

// Sample-kernel tile geometry
#define TH 13
#define TW 76
#define CG 4

// 302 MB scratch: sampled im2col matrix, layout [M=32768][K=2304] (k contiguous)
__device__ float g_samp[(size_t)MTOT * KTOT];
// tf32-rounded weights, [COUT][KTOT]
__device__ float g_wr[(size_t)COUT * KTOT];

// ============================ helpers ============================
__device__ __forceinline__ uint32_t smem_u32(const void* p) {
    uint32_t a;
    asm("{ .reg .u64 t; cvta.to.shared.u64 t, %1; cvt.u32.u64 %0, t; }"
        : "=r"(a) : "l"(p));
    return a;
}
__device__ __forceinline__ uint32_t tf32_rna(float v) {
    uint32_t r;
    asm("cvt.rna.tf32.f32 %0, %1;" : "=r"(r) : "f"(v));
    return r;
}
__device__ __forceinline__ void cp_async16(uint32_t dst, const void* src) {
    asm volatile("cp.async.cg.shared.global [%0], [%1], 16;"
                 :: "r"(dst), "l"(src) : "memory");
}
#define CP_COMMIT()  asm volatile("cp.async.commit_group;" ::: "memory")
#define CP_WAIT(n)   asm volatile("cp.async.wait_group %0;" :: "n"(n) : "memory")

__device__ __forceinline__ void ldsm_x4(uint32_t& r0, uint32_t& r1,
                                        uint32_t& r2, uint32_t& r3, uint32_t addr) {
    asm volatile("ldmatrix.sync.aligned.m8n8.x4.shared.b16 {%0,%1,%2,%3}, [%4];"
                 : "=r"(r0), "=r"(r1), "=r"(r2), "=r"(r3) : "r"(addr));
}
__device__ __forceinline__ void mma_tf32(float* c, const uint32_t* a, const uint32_t* b) {
    asm volatile(
        "mma.sync.aligned.m16n8k8.row.col.f32.tf32.tf32.f32 "
        "{%0,%1,%2,%3}, {%4,%5,%6,%7}, {%8,%9}, {%0,%1,%2,%3};"
        : "+f"(c[0]), "+f"(c[1]), "+f"(c[2]), "+f"(c[3])
        : "r"(a[0]), "r"(a[1]), "r"(a[2]), "r"(a[3]), "r"(b[0]), "r"(b[1]));
}

// ---------------- Kernel 1: sampling + weight rounding (fused launch) ----------------
// Blocks [0,512): OBB anchor sampling -> g_samp[M][K].
// Blocks [512,1088): round weights to tf32 -> g_wr (576 blocks * 1024 elems).
__global__ __launch_bounds__(256) void sample_kernel(
    const float* __restrict__ x,
    const float* __restrict__ obb,
    const float* __restrict__ wt,
    const unsigned* __restrict__ stride_ptr)
{
    __shared__ int    s_idx[576];
    __shared__ float4 s_w[576];
    __shared__ float  s_tile[CG * TH * TW];
    __shared__ float  s_out[64][37];    // [pixel][k_local], pitch 37

    const int tid = threadIdx.x;

    if (blockIdx.x >= 512) {
        // weight rounding: 589824 floats = 576 blocks * 256 thr * float4
        int i = ((blockIdx.x - 512) * 256 + tid) * 4;
        float4 v = *(const float4*)(wt + i);
        v.x = __uint_as_float(tf32_rna(v.x));
        v.y = __uint_as_float(tf32_rna(v.y));
        v.z = __uint_as_float(tf32_rna(v.z));
        v.w = __uint_as_float(tf32_rna(v.w));
        *(float4*)(g_wr + i) = v;
        return;
    }

    const int m0  = blockIdx.x * 64;
    const int n   = m0 >> 14;
    const int hw0 = m0 & 16383;
    const int h   = hw0 >> 7;
    const int w0  = hw0 & 127;

    unsigned su = *stride_ptr;
    float s = (su < 0x00800000u) ? (float)su : __uint_as_float(su);

    for (int e = tid; e < 576; e += 256) {
        int tap = e >> 6;
        int p   = e & 63;
        int w   = w0 + p;
        const float* ob = obb + (size_t)n * 5 * 16384 + h * 128 + w;
        float xc = ob[0]         / s;
        float yc = ob[16384]     / s;
        float bw = ob[2 * 16384] / s;
        float bh = ob[3 * 16384] / s;
        float th = ob[4 * 16384];
        float sn, cs;
        __sincosf(th, &sn, &cs);
        float kx = (float)(tap % 3 - 1);
        float ky = (float)(tap / 3 - 1);
        float px = bw * (1.0f / 3.0f) * kx;
        float py = bh * (1.0f / 3.0f) * ky;
        float xa = cs * px - sn * py + xc;
        float ya = sn * px + cs * py + yc;
        float fx = floorf(xa), fy = floorf(ya);
        float lx = xa - fx,    ly = ya - fy;
        int r   = (int)fy - (h - 6);
        int col = (int)fx - (w0 - 6);
        r   = min(max(r, 0), TH - 2);
        col = min(max(col, 0), TW - 2);
        s_idx[e] = r * TW + col;
        s_w[e] = make_float4((1.f - ly) * (1.f - lx),
                             (1.f - ly) * lx,
                             ly * (1.f - lx),
                             ly * lx);
    }

    const float* xn = x + (size_t)n * CIN * 16384;

    for (int c0 = 0; c0 < CIN; c0 += CG) {
        __syncthreads();
        for (int i = tid; i < CG * TH * TW; i += 256) {
            int cc  = i / (TH * TW);
            int rem = i - cc * (TH * TW);
            int rr  = rem / TW;
            int col = rem - rr * TW;
            int gy = h - 6 + rr;
            int gx = w0 - 6 + col;
            float v = 0.f;
            if ((unsigned)gy < 128u && (unsigned)gx < 128u)
                v = __ldg(xn + (size_t)(c0 + cc) * 16384 + gy * 128 + gx);
            s_tile[i] = v;
        }
        __syncthreads();
        #pragma unroll
        for (int j = 0; j < 9; j++) {
            int t2 = tid + (j << 8);
            int cl = t2 / 576;
            int e  = t2 - cl * 576;
            const float* tb = s_tile + cl * (TH * TW);
            int ii = s_idx[e];
            float4 wv = s_w[e];
            float v = wv.x * tb[ii] + wv.y * tb[ii + 1]
                    + wv.z * tb[ii + TW] + wv.w * tb[ii + TW + 1];
            s_out[e & 63][cl * 9 + (e >> 6)] = __uint_as_float(tf32_rna(v));
        }
        __syncthreads();
        for (int i = tid; i < 576; i += 256) {
            int row = i / 9;
            int q   = i - row * 9;
            float4 v4 = make_float4(s_out[row][q * 4],     s_out[row][q * 4 + 1],
                                    s_out[row][q * 4 + 2], s_out[row][q * 4 + 3]);
            *(float4*)&g_samp[(size_t)(m0 + row) * KTOT + c0 * 9 + q * 4] = v4;
        }
    }
}

// ---------------- Kernel 2: mma.sync TF32 GEMM ----------------
// CTA: 256 couts (M, all) x 128 pixels (N). 512 threads, warps 4(M) x 4(N),
// warp tile 64x32. K chunks of 32, 3-stage cp.async pipeline.
// g_samp read exactly once; g_wr from L2.

#define PITCH   36
#define KCHUNK  32
#define NCHUNKS (KTOT / KCHUNK)               // 72
#define A_ROWS  256
#define B_ROWS  128
#define STAGE_FLOATS ((A_ROWS + B_ROWS) * PITCH)  // 13824
#define NSTAGE  3
#define SMEM_DYN (NSTAGE * STAGE_FLOATS * 4)      // 165888 B

__global__ __launch_bounds__(512, 1) void gemm_mma(float* __restrict__ out)
{
    extern __shared__ __align__(16) float sm[];

    const int tid  = threadIdx.x;
    const int lane = tid & 31;
    const int wid  = tid >> 5;
    const int lq   = lane >> 2;
    const int lt   = lane & 3;
    const int warp_m = (wid & 3) << 6;    // 0,64,128,192 (couts)
    const int warp_n = (wid >> 2) << 5;   // 0,32,64,96 (pixels)
    const int n0p = blockIdx.x << 7;      // pixel base

    const uint32_t sm_u = smem_u32(sm);

    // ldmatrix lane address components
    const uint32_t a_row = (uint32_t)(warp_m + (lane & 15));
    const uint32_t a_ko  = ((lane >> 4) & 1) << 2;
    // B x4: quads -> (bn,k0),(bn,k4),(bn+1,k0),(bn+1,k4)
    const uint32_t b_row = (uint32_t)(warp_n + ((lane >> 4) << 3) + (lane & 7));
    const uint32_t b_ko  = ((lane >> 3) & 1) << 2;

    float acc[4][4][4];
    #pragma unroll
    for (int i = 0; i < 4; i++)
        #pragma unroll
        for (int j = 0; j < 4; j++)
            #pragma unroll
            for (int r = 0; r < 4; r++)
                acc[i][j][r] = 0.f;

    auto stage = [&](int c, int buf) {
        uint32_t base = sm_u + (uint32_t)buf * (STAGE_FLOATS * 4);
        // A: 256 couts x 32 k  (2048 cp16 / 512 thr = 4 each)
        const float* Aw = g_wr + c * KCHUNK;
        #pragma unroll
        for (int i = 0; i < 4; i++) {
            int id = tid + (i << 9);
            int r  = id >> 3;
            int q  = id & 7;
            cp_async16(base + (uint32_t)(r * PITCH + q * 4) * 4,
                       Aw + (size_t)r * KTOT + q * 4);
        }
        // B: 128 pixels x 32 k  (1024 cp16 / 512 thr = 2 each)
        const float* Bg = g_samp + (size_t)n0p * KTOT + c * KCHUNK;
        uint32_t bb = base + (uint32_t)(A_ROWS * PITCH) * 4;
        #pragma unroll
        for (int i = 0; i < 2; i++) {
            int id = tid + (i << 9);
            int r  = id >> 3;
            int q  = id & 7;
            cp_async16(bb + (uint32_t)(r * PITCH + q * 4) * 4,
                       Bg + (size_t)r * KTOT + q * 4);
        }
        CP_COMMIT();
    };

    stage(0, 0);
    stage(1, 1);

    for (int c = 0; c < NCHUNKS; c++) {
        int buf = c % NSTAGE;
        if (c < NCHUNKS - 1) { CP_WAIT(1); } else { CP_WAIT(0); }
        __syncthreads();
        if (c + 2 < NCHUNKS)
            stage(c + 2, (c + 2) % NSTAGE);

        const uint32_t ab = sm_u + (uint32_t)buf * (STAGE_FLOATS * 4);
        const uint32_t bb = ab + (uint32_t)(A_ROWS * PITCH) * 4;

        #pragma unroll
        for (int s = 0; s < 4; s++) {
            const uint32_t ks = (uint32_t)(s << 3);
            uint32_t b[4][2];
            #pragma unroll
            for (int bp = 0; bp < 2; bp++) {
                uint32_t addr = bb + (uint32_t)((b_row + (bp << 4)) * PITCH + ks + b_ko) * 4;
                ldsm_x4(b[bp * 2][0], b[bp * 2][1], b[bp * 2 + 1][0], b[bp * 2 + 1][1], addr);
            }
            #pragma unroll
            for (int am = 0; am < 4; am++) {
                uint32_t a[4];
                uint32_t addr = ab + (uint32_t)((a_row + (am << 4)) * PITCH + ks + a_ko) * 4;
                ldsm_x4(a[0], a[1], a[2], a[3], addr);
                #pragma unroll
                for (int bn = 0; bn < 4; bn++)
                    mma_tf32(acc[am][bn], a, b[bn]);
            }
        }
        __syncthreads();
    }

    // Epilogue: out[img][cout][hw]
    #pragma unroll
    for (int am = 0; am < 4; am++) {
        #pragma unroll
        for (int bn = 0; bn < 4; bn++) {
            int cout = warp_m + (am << 4) + lq;
            int pix  = n0p + warp_n + (bn << 3) + (lt << 1);
            int img  = pix >> 14;
            int hw   = pix & 16383;
            float* p0 = out + ((size_t)img << 22) + ((size_t)cout << 14) + hw;
            *(float2*)p0 = make_float2(acc[am][bn][0], acc[am][bn][1]);
            *(float2*)(p0 + ((size_t)8 << 14)) =
                make_float2(acc[am][bn][2], acc[am][bn][3]);
        }
    }
}

extern "C" void kernel_launch(void* const* d_in, const int* in_sizes, int n_in,
                              void* d_out, int out_size) {
    const float*    x   = (const float*)d_in[0];
    const float*    obb = (const float*)d_in[1];
    const float*    wt  = (const float*)d_in[2];
    const unsigned* st  = (const unsigned*)d_in[3];
    float* out = (float*)d_out;

    cudaFuncSetAttribute(gemm_mma, cudaFuncAttributeMaxDynamicSharedMemorySize, SMEM_DYN);

    sample_kernel<<<512 + 576, 256>>>(x, obb, wt, st);
    gemm_mma<<<MTOT / 128, 512, SMEM_DYN>>>(out);
}

// round 11
// speedup vs baseline: 1.0464x; 1.0464x over previous
#include <cuda_runtime.h>
#include <cstdint>

// Problem constants
#define N_BATCH 2
#define CIN     256
#define COUT    256
#define KTOT    2304      // CIN * 9
#define MTOT    32768     // N * H * W

// Sample-kernel tile geometry
#define TH 13
#define TW 76
#define CG 4

// 302 MB scratch: sampled im2col matrix, layout [K=2304][M=32768] (m contiguous)
__device__ float g_samp[(size_t)KTOT * MTOT];
// tf32-rounded weights, [COUT][KTOT]
__device__ float g_wr[(size_t)COUT * KTOT];

// ============================ helpers ============================
__device__ __forceinline__ uint32_t smem_u32(const void* p) {
    uint32_t a;
    asm("{ .reg .u64 t; cvta.to.shared.u64 t, %1; cvt.u32.u64 %0, t; }"
        : "=r"(a) : "l"(p));
    return a;
}
__device__ __forceinline__ uint32_t tf32_rna(float v) {
    uint32_t r;
    asm("cvt.rna.tf32.f32 %0, %1;" : "=r"(r) : "f"(v));
    return r;
}
__device__ __forceinline__ void cp_async16(uint32_t dst, const void* src) {
    asm volatile("cp.async.cg.shared.global [%0], [%1], 16;"
                 :: "r"(dst), "l"(src) : "memory");
}
#define CP_COMMIT()  asm volatile("cp.async.commit_group;" ::: "memory")
#define CP_WAIT(n)   asm volatile("cp.async.wait_group %0;" :: "n"(n) : "memory")

__device__ __forceinline__ void ldsm_x4(uint32_t& r0, uint32_t& r1,
                                        uint32_t& r2, uint32_t& r3, uint32_t addr) {
    asm volatile("ldmatrix.sync.aligned.m8n8.x4.shared.b16 {%0,%1,%2,%3}, [%4];"
                 : "=r"(r0), "=r"(r1), "=r"(r2), "=r"(r3) : "r"(addr));
}
__device__ __forceinline__ void mma_tf32(float* c, const uint32_t* a, const uint32_t* b) {
    asm volatile(
        "mma.sync.aligned.m16n8k8.row.col.f32.tf32.tf32.f32 "
        "{%0,%1,%2,%3}, {%4,%5,%6,%7}, {%8,%9}, {%0,%1,%2,%3};"
        : "+f"(c[0]), "+f"(c[1]), "+f"(c[2]), "+f"(c[3])
        : "r"(a[0]), "r"(a[1]), "r"(a[2]), "r"(a[3]), "r"(b[0]), "r"(b[1]));
}

// ---------------- Kernel 1: sampling + weight rounding (fused launch) ----------------
// Blocks [0,512): OBB anchor sampling -> g_samp[K][M] (m contiguous, fast stores).
// Blocks [512,1088): round weights to tf32 -> g_wr.
__global__ __launch_bounds__(256) void sample_kernel(
    const float* __restrict__ x,
    const float* __restrict__ obb,
    const float* __restrict__ wt,
    const unsigned* __restrict__ stride_ptr)
{
    __shared__ int    s_idx[576];
    __shared__ float4 s_w[576];
    __shared__ float  s_tile[CG * TH * TW];

    const int tid = threadIdx.x;

    if (blockIdx.x >= 512) {
        int i = ((blockIdx.x - 512) * 256 + tid) * 4;
        float4 v = *(const float4*)(wt + i);
        v.x = __uint_as_float(tf32_rna(v.x));
        v.y = __uint_as_float(tf32_rna(v.y));
        v.z = __uint_as_float(tf32_rna(v.z));
        v.w = __uint_as_float(tf32_rna(v.w));
        *(float4*)(g_wr + i) = v;
        return;
    }

    const int m0  = blockIdx.x * 64;
    const int n   = m0 >> 14;
    const int hw0 = m0 & 16383;
    const int h   = hw0 >> 7;
    const int w0  = hw0 & 127;

    unsigned su = *stride_ptr;
    float s = (su < 0x00800000u) ? (float)su : __uint_as_float(su);

    for (int e = tid; e < 576; e += 256) {
        int tap = e >> 6;
        int p   = e & 63;
        int w   = w0 + p;
        const float* ob = obb + (size_t)n * 5 * 16384 + h * 128 + w;
        float xc = ob[0]         / s;
        float yc = ob[16384]     / s;
        float bw = ob[2 * 16384] / s;
        float bh = ob[3 * 16384] / s;
        float th = ob[4 * 16384];
        float sn, cs;
        __sincosf(th, &sn, &cs);
        float kx = (float)(tap % 3 - 1);
        float ky = (float)(tap / 3 - 1);
        float px = bw * (1.0f / 3.0f) * kx;
        float py = bh * (1.0f / 3.0f) * ky;
        float xa = cs * px - sn * py + xc;
        float ya = sn * px + cs * py + yc;
        float fx = floorf(xa), fy = floorf(ya);
        float lx = xa - fx,    ly = ya - fy;
        int r   = (int)fy - (h - 6);
        int col = (int)fx - (w0 - 6);
        r   = min(max(r, 0), TH - 2);
        col = min(max(col, 0), TW - 2);
        s_idx[e] = r * TW + col;
        s_w[e] = make_float4((1.f - ly) * (1.f - lx),
                             (1.f - ly) * lx,
                             ly * (1.f - lx),
                             ly * lx);
    }

    const float* xn = x + (size_t)n * CIN * 16384;

    for (int c0 = 0; c0 < CIN; c0 += CG) {
        __syncthreads();
        for (int i = tid; i < CG * TH * TW; i += 256) {
            int cc  = i / (TH * TW);
            int rem = i - cc * (TH * TW);
            int rr  = rem / TW;
            int col = rem - rr * TW;
            int gy = h - 6 + rr;
            int gx = w0 - 6 + col;
            float v = 0.f;
            if ((unsigned)gy < 128u && (unsigned)gx < 128u)
                v = __ldg(xn + (size_t)(c0 + cc) * 16384 + gy * 128 + gx);
            s_tile[i] = v;
        }
        __syncthreads();
        #pragma unroll
        for (int j = 0; j < 9; j++) {
            int t2 = tid + (j << 8);
            int cl = t2 / 576;
            int e  = t2 - cl * 576;
            const float* tb = s_tile + cl * (TH * TW);
            int ii = s_idx[e];
            float4 wv = s_w[e];
            float v = wv.x * tb[ii] + wv.y * tb[ii + 1]
                    + wv.z * tb[ii + TW] + wv.w * tb[ii + TW + 1];
            int tap = e >> 6;
            int p   = e & 63;
            g_samp[(size_t)((c0 + cl) * 9 + tap) * MTOT + m0 + p] =
                __uint_as_float(tf32_rna(v));
        }
    }
}

// ---------------- Kernel 2: mma.sync TF32 GEMM ----------------
// CTA: 256 couts (M, all) x 128 pixels (N). 512 threads, warps 4(M) x 4(N),
// warp tile 64x32. K chunks of 32, 3-stage cp.async, ONE barrier per chunk.
// A = weights SMEM [cout][k] pitch 36 (ldmatrix.x4 frags).
// B = pixels  SMEM [k][pix]  pitch 136 (conflict-free scalar LDS frags).

#define APITCH  36
#define BPITCH  136
#define KCHUNK  32
#define NCHUNKS (KTOT / KCHUNK)               // 72
#define A_SZ    (COUT * APITCH)               // 9216 floats
#define B_SZ    (KCHUNK * BPITCH)             // 4352 floats
#define STAGE_FLOATS (A_SZ + B_SZ)            // 13568
#define NSTAGE  3
#define SMEM_DYN (NSTAGE * STAGE_FLOATS * 4)  // 162816 B

__global__ __launch_bounds__(512, 1) void gemm_mma(float* __restrict__ out)
{
    extern __shared__ __align__(16) float sm[];

    const int tid  = threadIdx.x;
    const int lane = tid & 31;
    const int wid  = tid >> 5;
    const int lq   = lane >> 2;
    const int lt   = lane & 3;
    const int warp_m = (wid & 3) << 6;    // 0,64,128,192 (couts)
    const int warp_n = (wid >> 2) << 5;   // 0,32,64,96 (pixels)
    const int n0p = blockIdx.x << 7;      // pixel base

    const uint32_t sm_u = smem_u32(sm);

    const uint32_t a_row = (uint32_t)(warp_m + (lane & 15));
    const uint32_t a_ko  = ((lane >> 4) & 1) << 2;

    float acc[4][4][4];
    #pragma unroll
    for (int i = 0; i < 4; i++)
        #pragma unroll
        for (int j = 0; j < 4; j++)
            #pragma unroll
            for (int r = 0; r < 4; r++)
                acc[i][j][r] = 0.f;

    auto stage = [&](int c, int buf) {
        uint32_t base = sm_u + (uint32_t)buf * (STAGE_FLOATS * 4);
        // A: 256 couts x 32 k (2048 cp16 / 512 thr)
        const float* Aw = g_wr + c * KCHUNK;
        #pragma unroll
        for (int i = 0; i < 4; i++) {
            int id = tid + (i << 9);
            int r  = id >> 3;
            int q  = id & 7;
            cp_async16(base + (uint32_t)(r * APITCH + q * 4) * 4,
                       Aw + (size_t)r * KTOT + q * 4);
        }
        // B: 32 k-rows x 128 pixels from [K][M] scratch (coalesced 512B rows)
        uint32_t bb = base + (uint32_t)(A_SZ) * 4;
        const float* Bg = g_samp + (size_t)c * KCHUNK * MTOT + n0p;
        #pragma unroll
        for (int i = 0; i < 2; i++) {
            int id = tid + (i << 9);       // 0..1023
            int k  = id >> 5;              // 0..31
            int q  = id & 31;              // float4 within 128-pix row
            cp_async16(bb + (uint32_t)(k * BPITCH + q * 4) * 4,
                       Bg + (size_t)k * MTOT + q * 4);
        }
        CP_COMMIT();
    };

    stage(0, 0);
    stage(1, 1);

    for (int c = 0; c < NCHUNKS; c++) {
        int buf = c % NSTAGE;
        if (c < NCHUNKS - 1) { CP_WAIT(1); } else { CP_WAIT(0); }
        __syncthreads();                 // single barrier per chunk
        if (c + 2 < NCHUNKS)
            stage(c + 2, (c + 2) % NSTAGE);

        const uint32_t ab = sm_u + (uint32_t)buf * (STAGE_FLOATS * 4);
        const float* Bb = sm + (size_t)buf * STAGE_FLOATS + A_SZ;

        #pragma unroll
        for (int s = 0; s < 4; s++) {
            const uint32_t ks = (uint32_t)(s << 3);
            // B frags: conflict-free scalar LDS (pitch 136 ≡ 8 mod 32)
            const float* bp0 = Bb + (ks + lt) * BPITCH + warp_n + lq;
            uint32_t b[4][2];
            #pragma unroll
            for (int bn = 0; bn < 4; bn++) {
                b[bn][0] = __float_as_uint(bp0[bn << 3]);
                b[bn][1] = __float_as_uint(bp0[4 * BPITCH + (bn << 3)]);
            }
            #pragma unroll
            for (int am = 0; am < 4; am++) {
                uint32_t a[4];
                uint32_t addr = ab + (uint32_t)((a_row + (am << 4)) * APITCH + ks + a_ko) * 4;
                ldsm_x4(a[0], a[1], a[2], a[3], addr);
                #pragma unroll
                for (int bn = 0; bn < 4; bn++)
                    mma_tf32(acc[am][bn], a, b[bn]);
            }
        }
    }

    // Epilogue: out[img][cout][hw]
    #pragma unroll
    for (int am = 0; am < 4; am++) {
        #pragma unroll
        for (int bn = 0; bn < 4; bn++) {
            int cout = warp_m + (am << 4) + lq;
            int pix  = n0p + warp_n + (bn << 3) + (lt << 1);
            int img  = pix >> 14;
            int hw   = pix & 16383;
            float* p0 = out + ((size_t)img << 22) + ((size_t)cout << 14) + hw;
            *(float2*)p0 = make_float2(acc[am][bn][0], acc[am][bn][1]);
            *(float2*)(p0 + ((size_t)8 << 14)) =
                make_float2(acc[am][bn][2], acc[am][bn][3]);
        }
    }
}

extern "C" void kernel_launch(void* const* d_in, const int* in_sizes, int n_in,
                              void* d_out, int out_size) {
    const float*    x   = (const float*)d_in[0];
    const float*    obb = (const float*)d_in[1];
    const float*    wt  = (const float*)d_in[2];
    const unsigned* st  = (const unsigned*)d_in[3];
    float* out = (float*)d_out;

    cudaFuncSetAttribute(gemm_mma, cudaFuncAttributeMaxDynamicSharedMemorySize, SMEM_DYN);

    sample_kernel<<<512 + 576, 256>>>(x, obb, wt, st);
    gemm_mma<<<MTOT / 128, 512, SMEM_DYN>>>(out);
}

// round 12
// speedup vs baseline: 1.3187x; 1.2602x over previous
#include <cuda_runtime.h>
#include <cstdint>

// Problem constants
#define N_BATCH 2
#define CIN     256
#define COUT    256
#define KTOT    2304      // CIN * 9
#define MTOT    32768     // N * H * W

// Sample-kernel tile geometry
#define TH 13
#define TW 76
#define CG 4
#define TILE_F (CG * TH * TW)     // 3952 floats per stage buffer
#define CPB 64                    // channels per sampling block

// 302 MB scratch: sampled im2col matrix, layout [K=2304][M=32768] (m contiguous)
__device__ float g_samp[(size_t)KTOT * MTOT];
// tf32-rounded weights, [COUT][KTOT]
__device__ float g_wr[(size_t)COUT * KTOT];

// ============================ helpers ============================
__device__ __forceinline__ uint32_t smem_u32(const void* p) {
    uint32_t a;
    asm("{ .reg .u64 t; cvta.to.shared.u64 t, %1; cvt.u32.u64 %0, t; }"
        : "=r"(a) : "l"(p));
    return a;
}
__device__ __forceinline__ uint32_t tf32_rna(float v) {
    uint32_t r;
    asm("cvt.rna.tf32.f32 %0, %1;" : "=r"(r) : "f"(v));
    return r;
}
__device__ __forceinline__ void cp_async16(uint32_t dst, const void* src) {
    asm volatile("cp.async.cg.shared.global [%0], [%1], 16;"
                 :: "r"(dst), "l"(src) : "memory");
}
// 4-byte cp.async with runtime zero-fill (src_size = 0 or 4)
__device__ __forceinline__ void cp_async4_zfill(uint32_t dst, const void* src,
                                                uint32_t src_size) {
    asm volatile("cp.async.ca.shared.global [%0], [%1], 4, %2;"
                 :: "r"(dst), "l"(src), "r"(src_size) : "memory");
}
#define CP_COMMIT()  asm volatile("cp.async.commit_group;" ::: "memory")
#define CP_WAIT(n)   asm volatile("cp.async.wait_group %0;" :: "n"(n) : "memory")

__device__ __forceinline__ void ldsm_x4(uint32_t& r0, uint32_t& r1,
                                        uint32_t& r2, uint32_t& r3, uint32_t addr) {
    asm volatile("ldmatrix.sync.aligned.m8n8.x4.shared.b16 {%0,%1,%2,%3}, [%4];"
                 : "=r"(r0), "=r"(r1), "=r"(r2), "=r"(r3) : "r"(addr));
}
__device__ __forceinline__ void mma_tf32(float* c, const uint32_t* a, const uint32_t* b) {
    asm volatile(
        "mma.sync.aligned.m16n8k8.row.col.f32.tf32.tf32.f32 "
        "{%0,%1,%2,%3}, {%4,%5,%6,%7}, {%8,%9}, {%0,%1,%2,%3};"
        : "+f"(c[0]), "+f"(c[1]), "+f"(c[2]), "+f"(c[3])
        : "r"(a[0]), "r"(a[1]), "r"(a[2]), "r"(a[3]), "r"(b[0]), "r"(b[1]));
}

// ---------------- Kernel 1: sampling + weight rounding (fused launch) ----------------
// Blocks [0,2048): 64 pixels x 64 channels each -> g_samp[K][M].
//   bid>>2 = pixel group, bid&3 = channel quarter (adjacent bids share x tiles in L2).
// Blocks [2048,2624): round weights to tf32 -> g_wr.
__global__ __launch_bounds__(256) void sample_kernel(
    const float* __restrict__ x,
    const float* __restrict__ obb,
    const float* __restrict__ wt,
    const unsigned* __restrict__ stride_ptr)
{
    __shared__ int    s_idx[576];
    __shared__ float4 s_w[576];
    __shared__ float  s_tile[2][TILE_F];

    const int tid = threadIdx.x;

    if (blockIdx.x >= 2048) {
        int i = ((blockIdx.x - 2048) * 256 + tid) * 4;
        float4 v = *(const float4*)(wt + i);
        v.x = __uint_as_float(tf32_rna(v.x));
        v.y = __uint_as_float(tf32_rna(v.y));
        v.z = __uint_as_float(tf32_rna(v.z));
        v.w = __uint_as_float(tf32_rna(v.w));
        *(float4*)(g_wr + i) = v;
        return;
    }

    const int mg   = blockIdx.x >> 2;
    const int cbase = (blockIdx.x & 3) * CPB;
    const int m0  = mg * 64;
    const int n   = m0 >> 14;
    const int hw0 = m0 & 16383;
    const int h   = hw0 >> 7;
    const int w0  = hw0 & 127;

    unsigned su = *stride_ptr;
    float s = (su < 0x00800000u) ? (float)su : __uint_as_float(su);

    // Phase 0: per (pixel, tap) sampling metadata
    for (int e = tid; e < 576; e += 256) {
        int tap = e >> 6;
        int p   = e & 63;
        int w   = w0 + p;
        const float* ob = obb + (size_t)n * 5 * 16384 + h * 128 + w;
        float xc = ob[0]         / s;
        float yc = ob[16384]     / s;
        float bw = ob[2 * 16384] / s;
        float bh = ob[3 * 16384] / s;
        float th = ob[4 * 16384];
        float sn, cs;
        __sincosf(th, &sn, &cs);
        float kx = (float)(tap % 3 - 1);
        float ky = (float)(tap / 3 - 1);
        float px = bw * (1.0f / 3.0f) * kx;
        float py = bh * (1.0f / 3.0f) * ky;
        float xa = cs * px - sn * py + xc;
        float ya = sn * px + cs * py + yc;
        float fx = floorf(xa), fy = floorf(ya);
        float lx = xa - fx,    ly = ya - fy;
        int r   = (int)fy - (h - 6);
        int col = (int)fx - (w0 - 6);
        r   = min(max(r, 0), TH - 2);
        col = min(max(col, 0), TW - 2);
        s_idx[e] = r * TW + col;
        s_w[e] = make_float4((1.f - ly) * (1.f - lx),
                             (1.f - ly) * lx,
                             ly * (1.f - lx),
                             ly * lx);
    }

    const float* xn = x + (size_t)n * CIN * 16384;
    const uint32_t tile_u = smem_u32(&s_tile[0][0]);

    // async tile staging with zero-fill padding
    auto stage = [&](int it, int buf) {
        uint32_t dst0 = tile_u + (uint32_t)buf * (TILE_F * 4);
        int cb = cbase + it * CG;
        for (int i = tid; i < TILE_F; i += 256) {
            int cc  = i / (TH * TW);
            int rem = i - cc * (TH * TW);
            int rr  = rem / TW;
            int col = rem - rr * TW;
            int gy = h - 6 + rr;
            int gx = w0 - 6 + col;
            uint32_t valid = ((unsigned)gy < 128u && (unsigned)gx < 128u) ? 4u : 0u;
            int cgy = min(max(gy, 0), 127);
            int cgx = min(max(gx, 0), 127);
            cp_async4_zfill(dst0 + (uint32_t)i * 4,
                            xn + (size_t)(cb + cc) * 16384 + cgy * 128 + cgx,
                            valid);
        }
        CP_COMMIT();
    };

    __syncthreads();          // metadata ready
    stage(0, 0);

    for (int it = 0; it < CIN / CPB * (CPB / CG) / 4; it++) { } // (unused; keep compiler calm)

    #pragma unroll 1
    for (int it = 0; it < CPB / CG; it++) {          // 16 iterations
        if (it + 1 < CPB / CG) {
            stage(it + 1, (it + 1) & 1);
            CP_WAIT(1);
        } else {
            CP_WAIT(0);
        }
        __syncthreads();
        const float* tbuf = &s_tile[it & 1][0];
        int cb = cbase + it * CG;
        #pragma unroll
        for (int j = 0; j < 9; j++) {
            int t2 = tid + (j << 8);
            int cl = t2 / 576;
            int e  = t2 - cl * 576;
            const float* tb = tbuf + cl * (TH * TW);
            int ii = s_idx[e];
            float4 wv = s_w[e];
            float v = wv.x * tb[ii] + wv.y * tb[ii + 1]
                    + wv.z * tb[ii + TW] + wv.w * tb[ii + TW + 1];
            int tap = e >> 6;
            int p   = e & 63;
            g_samp[(size_t)((cb + cl) * 9 + tap) * MTOT + m0 + p] =
                __uint_as_float(tf32_rna(v));
        }
        __syncthreads();
    }
}

// ---------------- Kernel 2: mma.sync TF32 GEMM ----------------
// CTA: 128 couts (M) x 128 pixels (N), 256 threads (warps 2M x 4N, tile 64x32).
// K chunks of 32, 3-stage cp.async, single barrier per chunk. 2 CTAs/SM.
// A = weights SMEM [cout][k] pitch 36 (ldmatrix.x4 frags).
// B = pixels  SMEM [k][pix]  pitch 136 (conflict-free scalar LDS frags).

#define APITCH  36
#define BPITCH  136
#define KCHUNK  32
#define NCHUNKS (KTOT / KCHUNK)               // 72
#define A_ROWS  128
#define A_SZ    (A_ROWS * APITCH)             // 4608 floats
#define B_SZ    (KCHUNK * BPITCH)             // 4352 floats
#define STAGE_FLOATS (A_SZ + B_SZ)            // 8960
#define NSTAGE  3
#define SMEM_DYN (NSTAGE * STAGE_FLOATS * 4)  // 107520 B

__global__ __launch_bounds__(256, 2) void gemm_mma(float* __restrict__ out)
{
    extern __shared__ __align__(16) float sm[];

    const int tid  = threadIdx.x;
    const int lane = tid & 31;
    const int wid  = tid >> 5;
    const int lq   = lane >> 2;
    const int lt   = lane & 3;
    const int warp_m = (wid & 1) << 6;    // 0 / 64 (couts)
    const int warp_n = (wid >> 1) << 5;   // 0,32,64,96 (pixels)
    const int m0c = blockIdx.x << 7;      // cout half (x fastest -> L2 pair share)
    const int n0p = blockIdx.y << 7;      // pixel base

    const uint32_t sm_u = smem_u32(sm);

    const uint32_t a_row = (uint32_t)(warp_m + (lane & 15));
    const uint32_t a_ko  = ((lane >> 4) & 1) << 2;

    float acc[4][4][4];
    #pragma unroll
    for (int i = 0; i < 4; i++)
        #pragma unroll
        for (int j = 0; j < 4; j++)
            #pragma unroll
            for (int r = 0; r < 4; r++)
                acc[i][j][r] = 0.f;

    auto stage = [&](int c, int buf) {
        uint32_t base = sm_u + (uint32_t)buf * (STAGE_FLOATS * 4);
        // A: 128 couts x 32 k (1024 cp16 / 256 thr = 4 each)
        const float* Aw = g_wr + (size_t)m0c * KTOT + c * KCHUNK;
        #pragma unroll
        for (int i = 0; i < 4; i++) {
            int id = tid + (i << 8);
            int r  = id >> 3;
            int q  = id & 7;
            cp_async16(base + (uint32_t)(r * APITCH + q * 4) * 4,
                       Aw + (size_t)r * KTOT + q * 4);
        }
        // B: 32 k-rows x 128 pixels from [K][M] scratch (coalesced 512B rows)
        uint32_t bb = base + (uint32_t)(A_SZ) * 4;
        const float* Bg = g_samp + (size_t)c * KCHUNK * MTOT + n0p;
        #pragma unroll
        for (int i = 0; i < 4; i++) {
            int id = tid + (i << 8);       // 0..1023
            int k  = id >> 5;              // 0..31
            int q  = id & 31;              // float4 within 128-pix row
            cp_async16(bb + (uint32_t)(k * BPITCH + q * 4) * 4,
                       Bg + (size_t)k * MTOT + q * 4);
        }
        CP_COMMIT();
    };

    stage(0, 0);
    stage(1, 1);

    for (int c = 0; c < NCHUNKS; c++) {
        int buf = c % NSTAGE;
        if (c < NCHUNKS - 1) { CP_WAIT(1); } else { CP_WAIT(0); }
        __syncthreads();                 // single barrier per chunk
        if (c + 2 < NCHUNKS)
            stage(c + 2, (c + 2) % NSTAGE);

        const uint32_t ab = sm_u + (uint32_t)buf * (STAGE_FLOATS * 4);
        const float* Bb = sm + (size_t)buf * STAGE_FLOATS + A_SZ;

        #pragma unroll
        for (int s = 0; s < 4; s++) {
            const uint32_t ks = (uint32_t)(s << 3);
            // B frags: conflict-free scalar LDS (pitch 136 ≡ 8 mod 32)
            const float* bp0 = Bb + (ks + lt) * BPITCH + warp_n + lq;
            uint32_t b[4][2];
            #pragma unroll
            for (int bn = 0; bn < 4; bn++) {
                b[bn][0] = __float_as_uint(bp0[bn << 3]);
                b[bn][1] = __float_as_uint(bp0[4 * BPITCH + (bn << 3)]);
            }
            #pragma unroll
            for (int am = 0; am < 4; am++) {
                uint32_t a[4];
                uint32_t addr = ab + (uint32_t)((a_row + (am << 4)) * APITCH + ks + a_ko) * 4;
                ldsm_x4(a[0], a[1], a[2], a[3], addr);
                #pragma unroll
                for (int bn = 0; bn < 4; bn++)
                    mma_tf32(acc[am][bn], a, b[bn]);
            }
        }
    }

    // Epilogue: out[img][cout][hw]
    #pragma unroll
    for (int am = 0; am < 4; am++) {
        #pragma unroll
        for (int bn = 0; bn < 4; bn++) {
            int cout = m0c + warp_m + (am << 4) + lq;
            int pix  = n0p + warp_n + (bn << 3) + (lt << 1);
            int img  = pix >> 14;
            int hw   = pix & 16383;
            float* p0 = out + ((size_t)img << 22) + ((size_t)cout << 14) + hw;
            *(float2*)p0 = make_float2(acc[am][bn][0], acc[am][bn][1]);
            *(float2*)(p0 + ((size_t)8 << 14)) =
                make_float2(acc[am][bn][2], acc[am][bn][3]);
        }
    }
}

extern "C" void kernel_launch(void* const* d_in, const int* in_sizes, int n_in,
                              void* d_out, int out_size) {
    const float*    x   = (const float*)d_in[0];
    const float*    obb = (const float*)d_in[1];
    const float*    wt  = (const float*)d_in[2];
    const unsigned* st  = (const unsigned*)d_in[3];
    float* out = (float*)d_out;

    cudaFuncSetAttribute(gemm_mma, cudaFuncAttributeMaxDynamicSharedMemorySize, SMEM_DYN);

    sample_kernel<<<2048 + 576, 256>>>(x, obb, wt, st);
    dim3 g(COUT / 128, MTOT / 128);
    gemm_mma<<<g, 256, SMEM_DYN>>>(out);
}

// round 13
// speedup vs baseline: 1.4917x; 1.1312x over previous
#include <cuda_runtime.h>
#include <cstdint>

// Problem constants
#define N_BATCH 2
#define CIN     256
#define COUT    256
#define KTOT    2304      // CIN * 9
#define MTOT    32768     // N * H * W

// Sample kernel: 16x16 pixel tiles, 28x28 halo, 4 channels staged per buffer
#define HT 28
#define HSZ (HT * HT)             // 784
#define CG 4
#define TILE2_F (CG * HSZ)        // 3136 floats per stage buffer
#define NITEMS 2304               // 256 pixels * 9 taps
#define SMEM_SAMPLE (NITEMS * 4 + NITEMS * 16 + 2 * TILE2_F * 4)  // 71168 B

// 302 MB scratch: sampled im2col matrix, layout [K=2304][M=32768] (m contiguous)
__device__ float g_samp[(size_t)KTOT * MTOT];
// tf32-rounded weights, [COUT][KTOT]
__device__ float g_wr[(size_t)COUT * KTOT];

// ============================ helpers ============================
__device__ __forceinline__ uint32_t smem_u32(const void* p) {
    uint32_t a;
    asm("{ .reg .u64 t; cvta.to.shared.u64 t, %1; cvt.u32.u64 %0, t; }"
        : "=r"(a) : "l"(p));
    return a;
}
__device__ __forceinline__ uint32_t tf32_rna(float v) {
    uint32_t r;
    asm("cvt.rna.tf32.f32 %0, %1;" : "=r"(r) : "f"(v));
    return r;
}
__device__ __forceinline__ void cp_async16(uint32_t dst, const void* src) {
    asm volatile("cp.async.cg.shared.global [%0], [%1], 16;"
                 :: "r"(dst), "l"(src) : "memory");
}
// 4-byte cp.async with runtime zero-fill (src_size = 0 or 4)
__device__ __forceinline__ void cp_async4_zfill(uint32_t dst, const void* src,
                                                uint32_t src_size) {
    asm volatile("cp.async.ca.shared.global [%0], [%1], 4, %2;"
                 :: "r"(dst), "l"(src), "r"(src_size) : "memory");
}
#define CP_COMMIT()  asm volatile("cp.async.commit_group;" ::: "memory")
#define CP_WAIT(n)   asm volatile("cp.async.wait_group %0;" :: "n"(n) : "memory")

__device__ __forceinline__ void ldsm_x4(uint32_t& r0, uint32_t& r1,
                                        uint32_t& r2, uint32_t& r3, uint32_t addr) {
    asm volatile("ldmatrix.sync.aligned.m8n8.x4.shared.b16 {%0,%1,%2,%3}, [%4];"
                 : "=r"(r0), "=r"(r1), "=r"(r2), "=r"(r3) : "r"(addr));
}
__device__ __forceinline__ void mma_tf32(float* c, const uint32_t* a, const uint32_t* b) {
    asm volatile(
        "mma.sync.aligned.m16n8k8.row.col.f32.tf32.tf32.f32 "
        "{%0,%1,%2,%3}, {%4,%5,%6,%7}, {%8,%9}, {%0,%1,%2,%3};"
        : "+f"(c[0]), "+f"(c[1]), "+f"(c[2]), "+f"(c[3])
        : "r"(a[0]), "r"(a[1]), "r"(a[2]), "r"(a[3]), "r"(b[0]), "r"(b[1]));
}

// ---------------- Kernel 1: sampling + weight rounding (fused launch) ----------------
// Blocks [0,512): 16x16 pixel tile x 64 channels -> g_samp[K][M].
//   bid>>2 = tile (n, 8x8 grid), bid&3 = channel quarter.
// Blocks [512,1088): round weights to tf32 -> g_wr.
__global__ __launch_bounds__(256) void sample_kernel(
    const float* __restrict__ x,
    const float* __restrict__ obb,
    const float* __restrict__ wt,
    const unsigned* __restrict__ stride_ptr)
{
    extern __shared__ __align__(16) char smraw[];
    int*    s_idx  = (int*)smraw;                        // [2304]
    float4* s_w    = (float4*)(smraw + NITEMS * 4);      // [2304]
    float*  s_tile = (float*)(smraw + NITEMS * 20);      // [2][3136]

    const int tid = threadIdx.x;

    if (blockIdx.x >= 512) {
        int i = ((blockIdx.x - 512) * 256 + tid) * 4;
        float4 v = *(const float4*)(wt + i);
        v.x = __uint_as_float(tf32_rna(v.x));
        v.y = __uint_as_float(tf32_rna(v.y));
        v.z = __uint_as_float(tf32_rna(v.z));
        v.w = __uint_as_float(tf32_rna(v.w));
        *(float4*)(g_wr + i) = v;
        return;
    }

    const int tile = blockIdx.x >> 2;
    const int cq   = blockIdx.x & 3;        // channel quarter
    const int n    = tile >> 6;
    const int t    = tile & 63;
    const int h0   = (t >> 3) << 4;
    const int w0   = (t & 7) << 4;
    const int m0   = (n << 14) + h0 * 128 + w0;

    unsigned su = *stride_ptr;
    float s = (su < 0x00800000u) ? (float)su : __uint_as_float(su);

    // Phase 0: per (pixel, tap) metadata. e = tap*256 + p; thread writes e%256==tid,
    // and later reads the same set -> no barrier needed for metadata.
    for (int e = tid; e < NITEMS; e += 256) {
        int tap = e >> 8;
        int p   = e & 255;
        int ph  = p >> 4;
        int pw  = p & 15;
        int h   = h0 + ph;
        int w   = w0 + pw;
        const float* ob = obb + (size_t)n * 5 * 16384 + h * 128 + w;
        float xc = ob[0]         / s;
        float yc = ob[16384]     / s;
        float bw = ob[2 * 16384] / s;
        float bh = ob[3 * 16384] / s;
        float th = ob[4 * 16384];
        float sn, cs;
        __sincosf(th, &sn, &cs);
        float kx = (float)(tap % 3 - 1);
        float ky = (float)(tap / 3 - 1);
        float px = bw * (1.0f / 3.0f) * kx;
        float py = bh * (1.0f / 3.0f) * ky;
        float xa = cs * px - sn * py + xc;
        float ya = sn * px + cs * py + yc;
        float fx = floorf(xa), fy = floorf(ya);
        float lx = xa - fx,    ly = ya - fy;
        int r   = (int)fy - (h0 - 6);
        int col = (int)fx - (w0 - 6);
        r   = min(max(r, 0), HT - 2);
        col = min(max(col, 0), HT - 2);
        s_idx[e] = r * HT + col;
        s_w[e] = make_float4((1.f - ly) * (1.f - lx),
                             (1.f - ly) * lx,
                             ly * (1.f - lx),
                             ly * lx);
    }

    const float* xn = x + (size_t)n * CIN * 16384;
    const uint32_t tile_u = smem_u32(s_tile);

    // async 28x28 halo staging (4 channels) with zero-fill padding
    auto stage = [&](int it, int buf) {
        uint32_t dst0 = tile_u + (uint32_t)buf * (TILE2_F * 4);
        int cb = cq * 64 + it * CG;
        for (int i = tid; i < TILE2_F; i += 256) {
            int cc  = i / HSZ;
            int rem = i - cc * HSZ;
            int rr  = rem / HT;
            int col = rem - rr * HT;
            int gy = h0 - 6 + rr;
            int gx = w0 - 6 + col;
            uint32_t valid = ((unsigned)gy < 128u && (unsigned)gx < 128u) ? 4u : 0u;
            int cgy = min(max(gy, 0), 127);
            int cgx = min(max(gx, 0), 127);
            cp_async4_zfill(dst0 + (uint32_t)i * 4,
                            xn + (size_t)(cb + cc) * 16384 + cgy * 128 + cgx,
                            valid);
        }
        CP_COMMIT();
    };

    stage(0, 0);

    const int m_pix = m0 + ((tid >> 4) << 7) + (tid & 15);   // this thread's pixel

    #pragma unroll 1
    for (int it = 0; it < 64 / CG; it++) {           // 16 iterations
        if (it + 1 < 64 / CG) {
            stage(it + 1, (it + 1) & 1);
            CP_WAIT(1);
        } else {
            CP_WAIT(0);
        }
        __syncthreads();
        const float* tbuf = &s_tile[(it & 1) * TILE2_F];
        int cb = cq * 64 + it * CG;
        #pragma unroll
        for (int j = 0; j < 9; j++) {
            int e = (j << 8) + tid;
            int ii = s_idx[e];
            float4 wv = s_w[e];
            #pragma unroll
            for (int cl = 0; cl < CG; cl++) {
                const float* tb = tbuf + cl * HSZ;
                float v = wv.x * tb[ii] + wv.y * tb[ii + 1]
                        + wv.z * tb[ii + HT] + wv.w * tb[ii + HT + 1];
                g_samp[(size_t)((cb + cl) * 9 + j) * MTOT + m_pix] =
                    __uint_as_float(tf32_rna(v));
            }
        }
        __syncthreads();   // before next stage overwrites the other buffer
    }
}

// ---------------- Kernel 2: mma.sync TF32 GEMM (unchanged from R12) ----------------
// CTA: 128 couts (M) x 128 pixels (N), 256 threads (warps 2M x 4N, tile 64x32).
// K chunks of 32, 3-stage cp.async, single barrier per chunk. 2 CTAs/SM.

#define APITCH  36
#define BPITCH  136
#define KCHUNK  32
#define NCHUNKS (KTOT / KCHUNK)               // 72
#define A_ROWS  128
#define A_SZ    (A_ROWS * APITCH)             // 4608 floats
#define B_SZ    (KCHUNK * BPITCH)             // 4352 floats
#define STAGE_FLOATS (A_SZ + B_SZ)            // 8960
#define NSTAGE  3
#define SMEM_DYN (NSTAGE * STAGE_FLOATS * 4)  // 107520 B

__global__ __launch_bounds__(256, 2) void gemm_mma(float* __restrict__ out)
{
    extern __shared__ __align__(16) float sm[];

    const int tid  = threadIdx.x;
    const int lane = tid & 31;
    const int wid  = tid >> 5;
    const int lq   = lane >> 2;
    const int lt   = lane & 3;
    const int warp_m = (wid & 1) << 6;    // 0 / 64 (couts)
    const int warp_n = (wid >> 1) << 5;   // 0,32,64,96 (pixels)
    const int m0c = blockIdx.x << 7;      // cout half
    const int n0p = blockIdx.y << 7;      // pixel base

    const uint32_t sm_u = smem_u32(sm);

    const uint32_t a_row = (uint32_t)(warp_m + (lane & 15));
    const uint32_t a_ko  = ((lane >> 4) & 1) << 2;

    float acc[4][4][4];
    #pragma unroll
    for (int i = 0; i < 4; i++)
        #pragma unroll
        for (int j = 0; j < 4; j++)
            #pragma unroll
            for (int r = 0; r < 4; r++)
                acc[i][j][r] = 0.f;

    auto stage = [&](int c, int buf) {
        uint32_t base = sm_u + (uint32_t)buf * (STAGE_FLOATS * 4);
        const float* Aw = g_wr + (size_t)m0c * KTOT + c * KCHUNK;
        #pragma unroll
        for (int i = 0; i < 4; i++) {
            int id = tid + (i << 8);
            int r  = id >> 3;
            int q  = id & 7;
            cp_async16(base + (uint32_t)(r * APITCH + q * 4) * 4,
                       Aw + (size_t)r * KTOT + q * 4);
        }
        uint32_t bb = base + (uint32_t)(A_SZ) * 4;
        const float* Bg = g_samp + (size_t)c * KCHUNK * MTOT + n0p;
        #pragma unroll
        for (int i = 0; i < 4; i++) {
            int id = tid + (i << 8);
            int k  = id >> 5;
            int q  = id & 31;
            cp_async16(bb + (uint32_t)(k * BPITCH + q * 4) * 4,
                       Bg + (size_t)k * MTOT + q * 4);
        }
        CP_COMMIT();
    };

    stage(0, 0);
    stage(1, 1);

    for (int c = 0; c < NCHUNKS; c++) {
        int buf = c % NSTAGE;
        if (c < NCHUNKS - 1) { CP_WAIT(1); } else { CP_WAIT(0); }
        __syncthreads();
        if (c + 2 < NCHUNKS)
            stage(c + 2, (c + 2) % NSTAGE);

        const uint32_t ab = sm_u + (uint32_t)buf * (STAGE_FLOATS * 4);
        const float* Bb = sm + (size_t)buf * STAGE_FLOATS + A_SZ;

        #pragma unroll
        for (int s = 0; s < 4; s++) {
            const uint32_t ks = (uint32_t)(s << 3);
            const float* bp0 = Bb + (ks + lt) * BPITCH + warp_n + lq;
            uint32_t b[4][2];
            #pragma unroll
            for (int bn = 0; bn < 4; bn++) {
                b[bn][0] = __float_as_uint(bp0[bn << 3]);
                b[bn][1] = __float_as_uint(bp0[4 * BPITCH + (bn << 3)]);
            }
            #pragma unroll
            for (int am = 0; am < 4; am++) {
                uint32_t a[4];
                uint32_t addr = ab + (uint32_t)((a_row + (am << 4)) * APITCH + ks + a_ko) * 4;
                ldsm_x4(a[0], a[1], a[2], a[3], addr);
                #pragma unroll
                for (int bn = 0; bn < 4; bn++)
                    mma_tf32(acc[am][bn], a, b[bn]);
            }
        }
    }

    #pragma unroll
    for (int am = 0; am < 4; am++) {
        #pragma unroll
        for (int bn = 0; bn < 4; bn++) {
            int cout = m0c + warp_m + (am << 4) + lq;
            int pix  = n0p + warp_n + (bn << 3) + (lt << 1);
            int img  = pix >> 14;
            int hw   = pix & 16383;
            float* p0 = out + ((size_t)img << 22) + ((size_t)cout << 14) + hw;
            *(float2*)p0 = make_float2(acc[am][bn][0], acc[am][bn][1]);
            *(float2*)(p0 + ((size_t)8 << 14)) =
                make_float2(acc[am][bn][2], acc[am][bn][3]);
        }
    }
}

extern "C" void kernel_launch(void* const* d_in, const int* in_sizes, int n_in,
                              void* d_out, int out_size) {
    const float*    x   = (const float*)d_in[0];
    const float*    obb = (const float*)d_in[1];
    const float*    wt  = (const float*)d_in[2];
    const unsigned* st  = (const unsigned*)d_in[3];
    float* out = (float*)d_out;

    cudaFuncSetAttribute(sample_kernel, cudaFuncAttributeMaxDynamicSharedMemorySize, SMEM_SAMPLE);
    cudaFuncSetAttribute(gemm_mma, cudaFuncAttributeMaxDynamicSharedMemorySize, SMEM_DYN);

    sample_kernel<<<512 + 576, 256, SMEM_SAMPLE>>>(x, obb, wt, st);
    dim3 g(COUT / 128, MTOT / 128);
    gemm_mma<<<g, 256, SMEM_DYN>>>(out);
}

// round 15
// speedup vs baseline: 1.6031x; 1.0746x over previous
#include <cuda_runtime.h>
#include <cstdint>

// Problem constants
#define N_BATCH 2
#define CIN     256
#define COUT    256
#define KTOT    2304      // CIN * 9
#define MTOT    32768     // N * H * W

// Sample kernel: 16x16 pixel tiles, 28-row halo, pitch-29 cols, 4 ch interleaved
#define HROWS 28
#define HPITCH 29
#define NPOS  (HROWS * HPITCH)    // 812 positions
#define TILE_F (NPOS * 4)         // 3248 floats per buffer (float4 per pos)
#define NSTG  13                  // ceil(3248/256) staging elems per thread

// 302 MB scratch: sampled im2col matrix, layout [K=2304][M=32768] (m contiguous)
__device__ float g_samp[(size_t)KTOT * MTOT];
// tf32-rounded weights, [COUT][KTOT]
__device__ float g_wr[(size_t)COUT * KTOT];

// ============================ helpers ============================
__device__ __forceinline__ uint32_t smem_u32(const void* p) {
    uint32_t a;
    asm("{ .reg .u64 t; cvta.to.shared.u64 t, %1; cvt.u32.u64 %0, t; }"
        : "=r"(a) : "l"(p));
    return a;
}
__device__ __forceinline__ uint32_t tf32_rna(float v) {
    uint32_t r;
    asm("cvt.rna.tf32.f32 %0, %1;" : "=r"(r) : "f"(v));
    return r;
}
__device__ __forceinline__ void cp_async16(uint32_t dst, const void* src) {
    asm volatile("cp.async.cg.shared.global [%0], [%1], 16;"
                 :: "r"(dst), "l"(src) : "memory");
}
#define CP_COMMIT()  asm volatile("cp.async.commit_group;" ::: "memory")
#define CP_WAIT(n)   asm volatile("cp.async.wait_group %0;" :: "n"(n) : "memory")

__device__ __forceinline__ void ldsm_x4(uint32_t& r0, uint32_t& r1,
                                        uint32_t& r2, uint32_t& r3, uint32_t addr) {
    asm volatile("ldmatrix.sync.aligned.m8n8.x4.shared.b16 {%0,%1,%2,%3}, [%4];"
                 : "=r"(r0), "=r"(r1), "=r"(r2), "=r"(r3) : "r"(addr));
}
__device__ __forceinline__ void mma_tf32(float* c, const uint32_t* a, const uint32_t* b) {
    asm volatile(
        "mma.sync.aligned.m16n8k8.row.col.f32.tf32.tf32.f32 "
        "{%0,%1,%2,%3}, {%4,%5,%6,%7}, {%8,%9}, {%0,%1,%2,%3};"
        : "+f"(c[0]), "+f"(c[1]), "+f"(c[2]), "+f"(c[3])
        : "r"(a[0]), "r"(a[1]), "r"(a[2]), "r"(a[3]), "r"(b[0]), "r"(b[1]));
}

// ---------------- Kernel 1: sampling + weight rounding (fused launch) ----------------
// Blocks [0,512): 16x16 pixel tile x 64 channels -> g_samp[K][M].
//   bid>>2 = tile (n, 8x8 grid), bid&3 = channel quarter.
// Blocks [512,1088): round weights to tf32 -> g_wr.
__global__ __launch_bounds__(256, 2) void sample_kernel(
    const float* __restrict__ x,
    const float* __restrict__ obb,
    const float* __restrict__ wt,
    const unsigned* __restrict__ stride_ptr)
{
    __shared__ __align__(16) float s_tile[2][TILE_F];   // [buf][pos*4+ch]

    const int tid = threadIdx.x;

    if (blockIdx.x >= 512) {
        int i = ((blockIdx.x - 512) * 256 + tid) * 4;
        float4 v = *(const float4*)(wt + i);
        v.x = __uint_as_float(tf32_rna(v.x));
        v.y = __uint_as_float(tf32_rna(v.y));
        v.z = __uint_as_float(tf32_rna(v.z));
        v.w = __uint_as_float(tf32_rna(v.w));
        *(float4*)(g_wr + i) = v;
        return;
    }

    const int tile = blockIdx.x >> 2;
    const int cq   = blockIdx.x & 3;        // channel quarter
    const int n    = tile >> 6;
    const int t    = tile & 63;
    const int h0   = (t >> 3) << 4;
    const int w0   = (t & 7) << 4;
    const int m0   = (n << 14) + h0 * 128 + w0;

    unsigned su = *stride_ptr;
    float s = (su < 0x00800000u) ? (float)su : __uint_as_float(su);

    // ---- Phase 0: per-pixel metadata, kept entirely in registers ----
    int    ridx[9];
    float4 rw[9];
    {
        const int ph = tid >> 4;
        const int pw = tid & 15;
        const int h  = h0 + ph;
        const int w  = w0 + pw;
        const float* ob = obb + (size_t)n * 5 * 16384 + h * 128 + w;
        float xc = ob[0]         / s;
        float yc = ob[16384]     / s;
        float bw = ob[2 * 16384] / s;
        float bh = ob[3 * 16384] / s;
        float th = ob[4 * 16384];
        float sn, cs;
        __sincosf(th, &sn, &cs);
        #pragma unroll
        for (int tap = 0; tap < 9; tap++) {
            float kx = (float)(tap % 3 - 1);
            float ky = (float)(tap / 3 - 1);
            float px = bw * (1.0f / 3.0f) * kx;
            float py = bh * (1.0f / 3.0f) * ky;
            float xa = cs * px - sn * py + xc;
            float ya = sn * px + cs * py + yc;
            float fx = floorf(xa), fy = floorf(ya);
            float lx = xa - fx,    ly = ya - fy;
            int r   = (int)fy - (h0 - 6);
            int col = (int)fx - (w0 - 6);
            r   = min(max(r, 0), HROWS - 2);
            col = min(max(col, 0), HROWS - 2);   // cols used: [0,27]
            ridx[tap] = r * HPITCH + col;
            rw[tap] = make_float4((1.f - ly) * (1.f - lx),
                                  (1.f - ly) * lx,
                                  ly * (1.f - lx),
                                  ly * lx);
        }
    }

    // ---- Staging descriptors (packed): off[0:14) | dst[14:26) | valid[26] ----
    const float* xn = x + (size_t)n * CIN * 16384;
    uint32_t desc[NSTG];
    #pragma unroll
    for (int tt = 0; tt < NSTG; tt++) {
        int i = tid + tt * 256;
        uint32_t d = 0;
        if (i < TILE_F) {
            int ch  = i / NPOS;             // 0..3 (planar gmem iteration)
            int pos = i - ch * NPOS;
            int rr  = pos / HPITCH;
            int col = pos - rr * HPITCH;
            int gy = h0 - 6 + rr;
            int gx = w0 - 6 + col;
            int valid = (col < HROWS) & ((unsigned)gy < 128u) & ((unsigned)gx < 128u);
            int cgy = min(max(gy, 0), 127);
            int cgx = min(max(gx, 0), 127);
            uint32_t off = (uint32_t)(cgy * 128 + cgx);
            uint32_t dst = (uint32_t)(pos * 4 + ch);    // interleaved smem index
            d = off | (dst << 14) | ((uint32_t)valid << 26) | (1u << 27);
        }
        desc[tt] = d;
    }

    const int m_pix = m0 + ((tid >> 4) << 7) + (tid & 15);

    // ---- Prologue: load iteration 0 into registers ----
    float rv[NSTG];
    #pragma unroll
    for (int tt = 0; tt < NSTG; tt++) {
        uint32_t d = desc[tt];
        int ch = (tid + tt * 256) / NPOS;
        rv[tt] = 0.f;
        if ((d >> 26) & 1)
            rv[tt] = __ldg(xn + (size_t)(cq * 64 + ch) * 16384 + (d & 0x3FFF));
    }

    #pragma unroll 1
    for (int it = 0; it < 16; it++) {                 // 4 channels per iteration
        // scatter current regs into interleaved tile
        float* buf = &s_tile[it & 1][0];
        #pragma unroll
        for (int tt = 0; tt < NSTG; tt++) {
            uint32_t d = desc[tt];
            if (d >> 27)
                buf[(d >> 14) & 0xFFF] = rv[tt];
        }
        __syncthreads();

        // issue next iteration's loads (latency hidden under compute)
        if (it + 1 < 16) {
            int cb_next = cq * 64 + (it + 1) * 4;
            #pragma unroll
            for (int tt = 0; tt < NSTG; tt++) {
                uint32_t d = desc[tt];
                int ch = (tid + tt * 256) / NPOS;
                rv[tt] = 0.f;
                if ((d >> 26) & 1)
                    rv[tt] = __ldg(xn + (size_t)(cb_next + ch) * 16384 + (d & 0x3FFF));
            }
        }

        // bilinear gather: one LDS.128 per corner serves 4 channels
        const float4* tb = (const float4*)buf;
        const int cb = cq * 64 + it * 4;
        #pragma unroll
        for (int j = 0; j < 9; j++) {
            int ii = ridx[j];
            float4 wv = rw[j];
            float4 c00 = tb[ii];
            float4 c01 = tb[ii + 1];
            float4 c10 = tb[ii + HPITCH];
            float4 c11 = tb[ii + HPITCH + 1];
            float v0 = wv.x * c00.x + wv.y * c01.x + wv.z * c10.x + wv.w * c11.x;
            float v1 = wv.x * c00.y + wv.y * c01.y + wv.z * c10.y + wv.w * c11.y;
            float v2 = wv.x * c00.z + wv.y * c01.z + wv.z * c10.z + wv.w * c11.z;
            float v3 = wv.x * c00.w + wv.y * c01.w + wv.z * c10.w + wv.w * c11.w;
            size_t kb = (size_t)(cb * 9 + j) * MTOT + m_pix;
            g_samp[kb]                      = __uint_as_float(tf32_rna(v0));
            g_samp[kb + (size_t)9 * MTOT]   = __uint_as_float(tf32_rna(v1));
            g_samp[kb + (size_t)18 * MTOT]  = __uint_as_float(tf32_rna(v2));
            g_samp[kb + (size_t)27 * MTOT]  = __uint_as_float(tf32_rna(v3));
        }
        __syncthreads();
    }
}

// ---------------- Kernel 2: mma.sync TF32 GEMM (unchanged from R12/R13) ----------------
// CTA: 128 couts (M) x 128 pixels (N), 256 threads (warps 2M x 4N, tile 64x32).
// K chunks of 32, 3-stage cp.async, single barrier per chunk. 2 CTAs/SM.

#define APITCH  36
#define BPITCH  136
#define KCHUNK  32
#define NCHUNKS (KTOT / KCHUNK)               // 72
#define A_ROWS  128
#define A_SZ    (A_ROWS * APITCH)             // 4608 floats
#define B_SZ    (KCHUNK * BPITCH)             // 4352 floats
#define STAGE_FLOATS (A_SZ + B_SZ)            // 8960
#define NSTAGE  3
#define SMEM_DYN (NSTAGE * STAGE_FLOATS * 4)  // 107520 B

__global__ __launch_bounds__(256, 2) void gemm_mma(float* __restrict__ out)
{
    extern __shared__ __align__(16) float sm[];

    const int tid  = threadIdx.x;
    const int lane = tid & 31;
    const int wid  = tid >> 5;
    const int lq   = lane >> 2;
    const int lt   = lane & 3;
    const int warp_m = (wid & 1) << 6;    // 0 / 64 (couts)
    const int warp_n = (wid >> 1) << 5;   // 0,32,64,96 (pixels)
    const int m0c = blockIdx.x << 7;      // cout half
    const int n0p = blockIdx.y << 7;      // pixel base

    const uint32_t sm_u = smem_u32(sm);

    const uint32_t a_row = (uint32_t)(warp_m + (lane & 15));
    const uint32_t a_ko  = ((lane >> 4) & 1) << 2;

    float acc[4][4][4];
    #pragma unroll
    for (int i = 0; i < 4; i++)
        #pragma unroll
        for (int j = 0; j < 4; j++)
            #pragma unroll
            for (int r = 0; r < 4; r++)
                acc[i][j][r] = 0.f;

    auto stage = [&](int c, int buf) {
        uint32_t base = sm_u + (uint32_t)buf * (STAGE_FLOATS * 4);
        const float* Aw = g_wr + (size_t)m0c * KTOT + c * KCHUNK;
        #pragma unroll
        for (int i = 0; i < 4; i++) {
            int id = tid + (i << 8);
            int r  = id >> 3;
            int q  = id & 7;
            cp_async16(base + (uint32_t)(r * APITCH + q * 4) * 4,
                       Aw + (size_t)r * KTOT + q * 4);
        }
        uint32_t bb = base + (uint32_t)(A_SZ) * 4;
        const float* Bg = g_samp + (size_t)c * KCHUNK * MTOT + n0p;
        #pragma unroll
        for (int i = 0; i < 4; i++) {
            int id = tid + (i << 8);
            int k  = id >> 5;
            int q  = id & 31;
            cp_async16(bb + (uint32_t)(k * BPITCH + q * 4) * 4,
                       Bg + (size_t)k * MTOT + q * 4);
        }
        CP_COMMIT();
    };

    stage(0, 0);
    stage(1, 1);

    for (int c = 0; c < NCHUNKS; c++) {
        int buf = c % NSTAGE;
        if (c < NCHUNKS - 1) { CP_WAIT(1); } else { CP_WAIT(0); }
        __syncthreads();
        if (c + 2 < NCHUNKS)
            stage(c + 2, (c + 2) % NSTAGE);

        const uint32_t ab = sm_u + (uint32_t)buf * (STAGE_FLOATS * 4);
        const float* Bb = sm + (size_t)buf * STAGE_FLOATS + A_SZ;

        #pragma unroll
        for (int s = 0; s < 4; s++) {
            const uint32_t ks = (uint32_t)(s << 3);
            const float* bp0 = Bb + (ks + lt) * BPITCH + warp_n + lq;
            uint32_t b[4][2];
            #pragma unroll
            for (int bn = 0; bn < 4; bn++) {
                b[bn][0] = __float_as_uint(bp0[bn << 3]);
                b[bn][1] = __float_as_uint(bp0[4 * BPITCH + (bn << 3)]);
            }
            #pragma unroll
            for (int am = 0; am < 4; am++) {
                uint32_t a[4];
                uint32_t addr = ab + (uint32_t)((a_row + (am << 4)) * APITCH + ks + a_ko) * 4;
                ldsm_x4(a[0], a[1], a[2], a[3], addr);
                #pragma unroll
                for (int bn = 0; bn < 4; bn++)
                    mma_tf32(acc[am][bn], a, b[bn]);
            }
        }
    }

    #pragma unroll
    for (int am = 0; am < 4; am++) {
        #pragma unroll
        for (int bn = 0; bn < 4; bn++) {
            int cout = m0c + warp_m + (am << 4) + lq;
            int pix  = n0p + warp_n + (bn << 3) + (lt << 1);
            int img  = pix >> 14;
            int hw   = pix & 16383;
            float* p0 = out + ((size_t)img << 22) + ((size_t)cout << 14) + hw;
            *(float2*)p0 = make_float2(acc[am][bn][0], acc[am][bn][1]);
            *(float2*)(p0 + ((size_t)8 << 14)) =
                make_float2(acc[am][bn][2], acc[am][bn][3]);
        }
    }
}

extern "C" void kernel_launch(void* const* d_in, const int* in_sizes, int n_in,
                              void* d_out, int out_size) {
    const float*    x   = (const float*)d_in[0];
    const float*    obb = (const float*)d_in[1];
    const float*    wt  = (const float*)d_in[2];
    const unsigned* st  = (const unsigned*)d_in[3];
    float* out = (float*)d_out;

    cudaFuncSetAttribute(gemm_mma, cudaFuncAttributeMaxDynamicSharedMemorySize, SMEM_DYN);

    sample_kernel<<<512 + 576, 256>>>(x, obb, wt, st);
    dim3 g(COUT / 128, MTOT / 128);
    gemm_mma<<<g, 256, SMEM_DYN>>>(out);
}